// round 10
// baseline (speedup 1.0000x reference)
#include <cuda_runtime.h>
#include <cuda_bf16.h>

// FastGaussianModel: values[m] = sum_n exp(-0.5 * sum_d (p[m,d]-pos[n,d])^2 * iv[n,d]) * I[n]
// log2-domain Horner form per gaussian:
//   e = C + sum_d p_d * (A_d * p_d + B_d),   value += ex2(e) * I
//
// R9 version:
//  - fma.rn.f32x2: 2 gaussians per instruction (pair-interleaved smem table)
//  - 4 points per thread (8 B LDS per point-gaussian pair)
//  - NSPLIT=16 (NP=64/slice): 1568 blocks x 4 warps = 6272 warps (~42/SM)
//    -> R7's occupancy with R8's lean instruction stream. MUFU floor ~12.3us.
//  - fused deterministic last-block reduction (wrapping atomicInc, graph-safe)

#define BLOCK   128
#define PPT     4              // points per thread
#define NSPLIT  16
#define NP      64             // gaussians per block (per N-slice)
#define NPAIR   (NP / 2)
#define PTS_PER_BLOCK (BLOCK * PPT)
#define MAXM    50176          // >= M=50000
#define MAXSLICE 128           // >= ceil(MAXM / PTS_PER_BLOCK)
#define EPS     1e-6f

__device__ float g_partial[NSPLIT][MAXM];
__device__ unsigned int g_count[MAXSLICE];   // zero-init; wraps to 0 each use

typedef unsigned long long u64;

__device__ __forceinline__ float ex2f(float x) {
    float y;
    asm("ex2.approx.ftz.f32 %0, %1;" : "=f"(y) : "f"(x));
    return y;
}
__device__ __forceinline__ u64 fma2(u64 a, u64 b, u64 c) {
    u64 d;
    asm("fma.rn.f32x2 %0, %1, %2, %3;" : "=l"(d) : "l"(a), "l"(b), "l"(c));
    return d;
}
__device__ __forceinline__ u64 pack2(float lo, float hi) {
    u64 r;
    asm("mov.b64 %0, {%1, %2};" : "=l"(r) : "f"(lo), "f"(hi));
    return r;
}
__device__ __forceinline__ void unpack2(u64 v, float& lo, float& hi) {
    asm("mov.b64 {%0, %1}, %2;" : "=f"(lo), "=f"(hi) : "l"(v));
}

__global__ __launch_bounds__(BLOCK)
void gauss_eval_kernel(const float* __restrict__ points,
                       const float* __restrict__ positions,
                       const float* __restrict__ log_scales,
                       const float* __restrict__ intensities,
                       float* __restrict__ out,
                       int M, int N)
{
    // Pair-interleaved coefficient table. Each ulonglong2 = two packed f32x2:
    //   TA[j] = { {A0,A0'}, {A1,A1'} }   TB[j] = { {A2,A2'}, { C, C' } }
    //   TC[j] = { {B0,B0'}, {B1,B1'} }   TD[j] = { {B2,B2'}, { I, I' } }
    __shared__ ulonglong2 TA[NPAIR], TB[NPAIR], TC[NPAIR], TD[NPAIR];
    __shared__ unsigned int s_ticket;

    const float L = 1.4426950408889634f;   // log2(e)
    const int tid = threadIdx.x;

    // ---- per-block precompute of this N-slice's table ----
    if (tid < NP) {
        int g = blockIdx.y * NP + tid;
        float A0 = 0.f, A1 = 0.f, A2 = 0.f, C = 0.f;
        float B0 = 0.f, B1 = 0.f, B2 = 0.f, I = 0.f;  // zero pad: ex2(0)*0 = 0
        if (g < N) {
            float ls0 = log_scales[3*g + 0];
            float ls1 = log_scales[3*g + 1];
            float ls2 = log_scales[3*g + 2];
            float q0  = positions[3*g + 0];
            float q1  = positions[3*g + 1];
            float q2  = positions[3*g + 2];
            I = intensities[g];

            float iv0 = 1.0f / (expf(2.0f * ls0) + EPS);
            float iv1 = 1.0f / (expf(2.0f * ls1) + EPS);
            float iv2 = 1.0f / (expf(2.0f * ls2) + EPS);

            A0 = -0.5f * L * iv0;
            A1 = -0.5f * L * iv1;
            A2 = -0.5f * L * iv2;
            B0 = L * iv0 * q0;
            B1 = L * iv1 * q1;
            B2 = L * iv2 * q2;
            C  = A0*q0*q0 + A1*q1*q1 + A2*q2*q2;
        }
        int j = tid >> 1, l = tid & 1;
        float* fTA = (float*)TA;  float* fTB = (float*)TB;
        float* fTC = (float*)TC;  float* fTD = (float*)TD;
        fTA[4*j + 0 + l] = A0;  fTA[4*j + 2 + l] = A1;
        fTB[4*j + 0 + l] = A2;  fTB[4*j + 2 + l] = C;
        fTC[4*j + 0 + l] = B0;  fTC[4*j + 2 + l] = B1;
        fTD[4*j + 0 + l] = B2;  fTD[4*j + 2 + l] = I;
    }
    __syncthreads();

    // ---- four points per thread (broadcast-packed coords, 3 u64 per point) ----
    int mbase = blockIdx.x * PTS_PER_BLOCK + tid;
    int midx[PPT];
    u64 P0[PPT], P1[PPT], P2[PPT];
    u64 acc[PPT];
    #pragma unroll
    for (int k = 0; k < PPT; ++k) {
        int m = mbase + k * BLOCK;
        midx[k] = m;
        int mc = m < M ? m : M - 1;
        float p0 = points[3*mc + 0];
        float p1 = points[3*mc + 1];
        float p2 = points[3*mc + 2];
        P0[k] = pack2(p0, p0);
        P1[k] = pack2(p1, p1);
        P2[k] = pack2(p2, p2);
        acc[k] = 0ull;
    }

    #pragma unroll 4
    for (int j = 0; j < NPAIR; ++j) {
        ulonglong2 ta = TA[j];
        ulonglong2 tb = TB[j];
        ulonglong2 tc = TC[j];
        ulonglong2 td = TD[j];

        #pragma unroll
        for (int k = 0; k < PPT; ++k) {
            // t_d = A_d*p_d + B_d (parallel), e = C + sum p_d * t_d
            u64 t0 = fma2(ta.x, P0[k], tc.x);
            u64 t1 = fma2(ta.y, P1[k], tc.y);
            u64 t2 = fma2(tb.x, P2[k], td.x);
            u64 e  = fma2(P0[k], t0, tb.y);
            e = fma2(P1[k], t1, e);
            e = fma2(P2[k], t2, e);

            float e0, e1;
            unpack2(e, e0, e1);
            float g0 = ex2f(e0), g1 = ex2f(e1);
            acc[k] = fma2(pack2(g0, g1), td.y, acc[k]);
        }
    }

    #pragma unroll
    for (int k = 0; k < PPT; ++k) {
        float s0, s1;
        unpack2(acc[k], s0, s1);
        if (midx[k] < M) g_partial[blockIdx.y][midx[k]] = s0 + s1;
    }

    // ---- fused deterministic reduction: last block of this x-slice sums all slices ----
    __threadfence();
    if (tid == 0) {
        s_ticket = atomicInc(&g_count[blockIdx.x], NSPLIT - 1);
    }
    __syncthreads();
    if (s_ticket == NSPLIT - 1) {
        #pragma unroll
        for (int k = 0; k < PPT; ++k) {
            int m = midx[k];
            if (m < M) {
                float s = 0.0f;
                #pragma unroll
                for (int q = 0; q < NSPLIT; ++q) s += __ldcg(&g_partial[q][m]);
                out[m] = s;
            }
        }
    }
}

extern "C" void kernel_launch(void* const* d_in, const int* in_sizes, int n_in,
                              void* d_out, int out_size)
{
    const float* points      = (const float*)d_in[0];
    const float* positions   = (const float*)d_in[1];
    const float* log_scales  = (const float*)d_in[2];
    const float* intensities = (const float*)d_in[3];
    float* out = (float*)d_out;

    int M = in_sizes[0] / 3;
    int N = in_sizes[3];
    if (M > MAXM) M = MAXM;                 // scratch capacity (problem: M=50000)
    if (N > NSPLIT * NP) N = NSPLIT * NP;   // table capacity (problem: N=1024)

    dim3 grid((M + PTS_PER_BLOCK - 1) / PTS_PER_BLOCK, NSPLIT);
    gauss_eval_kernel<<<grid, BLOCK>>>(points, positions, log_scales, intensities,
                                       out, M, N);
}

// round 13
// speedup vs baseline: 1.4444x; 1.4444x over previous
#include <cuda_runtime.h>
#include <cuda_bf16.h>

// FastGaussianModel: values[m] = sum_n exp(-0.5 * sum_d (p[m,d]-pos[n,d])^2 * iv[n,d]) * I[n]
// log2-domain Horner form per gaussian:
//   e = C + sum_d p_d * (A_d * p_d + B_d),   value += ex2(e) * I
//
// R11 version (un-fused, single-wave):
//  - fma.rn.f32x2: 2 gaussians per instruction (pair-interleaved smem table)
//  - BLOCK=256, 4 points per thread, NSPLIT=12 -> grid (49,12) = 588 blocks
//    = ONE clean wave at 4 CTAs/SM (wave-quantization was R10's killer)
//  - no fused reduction (threadfence tail cost > separate launch): separate
//    float4-vectorized reduce kernel (12x LDG.128 per thread, MLP=12)

#define BLOCK   256
#define PPT     4              // points per thread
#define NSPLIT  12
#define NP      88             // gaussians per block slice (12*88=1056 >= 1024, zero-padded)
#define NPAIR   (NP / 2)
#define PTS_PER_BLOCK (BLOCK * PPT)
#define MAXM    50176          // >= M=50000
#define EPS     1e-6f

__device__ float g_partial[NSPLIT][MAXM];

typedef unsigned long long u64;

__device__ __forceinline__ float ex2f(float x) {
    float y;
    asm("ex2.approx.ftz.f32 %0, %1;" : "=f"(y) : "f"(x));
    return y;
}
__device__ __forceinline__ u64 fma2(u64 a, u64 b, u64 c) {
    u64 d;
    asm("fma.rn.f32x2 %0, %1, %2, %3;" : "=l"(d) : "l"(a), "l"(b), "l"(c));
    return d;
}
__device__ __forceinline__ u64 pack2(float lo, float hi) {
    u64 r;
    asm("mov.b64 %0, {%1, %2};" : "=l"(r) : "f"(lo), "f"(hi));
    return r;
}
__device__ __forceinline__ void unpack2(u64 v, float& lo, float& hi) {
    asm("mov.b64 {%0, %1}, %2;" : "=f"(lo), "=f"(hi) : "l"(v));
}

__global__ __launch_bounds__(BLOCK, 4)
void gauss_eval_kernel(const float* __restrict__ points,
                       const float* __restrict__ positions,
                       const float* __restrict__ log_scales,
                       const float* __restrict__ intensities,
                       int M, int N)
{
    // Pair-interleaved coefficient table. Each ulonglong2 = two packed f32x2:
    //   TA[j] = { {A0,A0'}, {A1,A1'} }   TB[j] = { {A2,A2'}, { C, C' } }
    //   TC[j] = { {B0,B0'}, {B1,B1'} }   TD[j] = { {B2,B2'}, { I, I' } }
    __shared__ ulonglong2 TA[NPAIR], TB[NPAIR], TC[NPAIR], TD[NPAIR];

    const float L = 1.4426950408889634f;   // log2(e)
    const int tid = threadIdx.x;

    // ---- per-block precompute of this N-slice's table ----
    if (tid < NP) {
        int g = blockIdx.y * NP + tid;
        float A0 = 0.f, A1 = 0.f, A2 = 0.f, C = 0.f;
        float B0 = 0.f, B1 = 0.f, B2 = 0.f, I = 0.f;  // zero pad: ex2(0)*0 = 0
        if (g < N) {
            float ls0 = log_scales[3*g + 0];
            float ls1 = log_scales[3*g + 1];
            float ls2 = log_scales[3*g + 2];
            float q0  = positions[3*g + 0];
            float q1  = positions[3*g + 1];
            float q2  = positions[3*g + 2];
            I = intensities[g];

            float iv0 = 1.0f / (expf(2.0f * ls0) + EPS);
            float iv1 = 1.0f / (expf(2.0f * ls1) + EPS);
            float iv2 = 1.0f / (expf(2.0f * ls2) + EPS);

            A0 = -0.5f * L * iv0;
            A1 = -0.5f * L * iv1;
            A2 = -0.5f * L * iv2;
            B0 = L * iv0 * q0;
            B1 = L * iv1 * q1;
            B2 = L * iv2 * q2;
            C  = A0*q0*q0 + A1*q1*q1 + A2*q2*q2;
        }
        int j = tid >> 1, l = tid & 1;
        float* fTA = (float*)TA;  float* fTB = (float*)TB;
        float* fTC = (float*)TC;  float* fTD = (float*)TD;
        fTA[4*j + 0 + l] = A0;  fTA[4*j + 2 + l] = A1;
        fTB[4*j + 0 + l] = A2;  fTB[4*j + 2 + l] = C;
        fTC[4*j + 0 + l] = B0;  fTC[4*j + 2 + l] = B1;
        fTD[4*j + 0 + l] = B2;  fTD[4*j + 2 + l] = I;
    }
    __syncthreads();

    // ---- four points per thread (broadcast-packed coords, 3 u64 per point) ----
    int mbase = blockIdx.x * PTS_PER_BLOCK + tid;
    int midx[PPT];
    u64 P0[PPT], P1[PPT], P2[PPT];
    u64 acc[PPT];
    #pragma unroll
    for (int k = 0; k < PPT; ++k) {
        int m = mbase + k * BLOCK;
        midx[k] = m;
        int mc = m < M ? m : M - 1;
        float p0 = points[3*mc + 0];
        float p1 = points[3*mc + 1];
        float p2 = points[3*mc + 2];
        P0[k] = pack2(p0, p0);
        P1[k] = pack2(p1, p1);
        P2[k] = pack2(p2, p2);
        acc[k] = 0ull;
    }

    #pragma unroll 4
    for (int j = 0; j < NPAIR; ++j) {
        ulonglong2 ta = TA[j];
        ulonglong2 tb = TB[j];
        ulonglong2 tc = TC[j];
        ulonglong2 td = TD[j];

        #pragma unroll
        for (int k = 0; k < PPT; ++k) {
            // t_d = A_d*p_d + B_d (parallel), e = C + sum p_d * t_d
            u64 t0 = fma2(ta.x, P0[k], tc.x);
            u64 t1 = fma2(ta.y, P1[k], tc.y);
            u64 t2 = fma2(tb.x, P2[k], td.x);
            u64 e  = fma2(P0[k], t0, tb.y);
            e = fma2(P1[k], t1, e);
            e = fma2(P2[k], t2, e);

            float e0, e1;
            unpack2(e, e0, e1);
            float g0 = ex2f(e0), g1 = ex2f(e1);
            acc[k] = fma2(pack2(g0, g1), td.y, acc[k]);
        }
    }

    #pragma unroll
    for (int k = 0; k < PPT; ++k) {
        float s0, s1;
        unpack2(acc[k], s0, s1);
        if (midx[k] < M) g_partial[blockIdx.y][midx[k]] = s0 + s1;
    }
}

__global__ __launch_bounds__(256)
void reduce_kernel(float* __restrict__ out, int M)
{
    // float4-vectorized: each thread sums NSPLIT partial rows for 4 points.
    int i = blockIdx.x * 256 + threadIdx.x;      // float4 index
    int m = i * 4;
    if (m + 3 < M) {
        float4 s = make_float4(0.f, 0.f, 0.f, 0.f);
        #pragma unroll
        for (int q = 0; q < NSPLIT; ++q) {
            float4 v = *reinterpret_cast<const float4*>(&g_partial[q][m]);
            s.x += v.x; s.y += v.y; s.z += v.z; s.w += v.w;
        }
        *reinterpret_cast<float4*>(&out[m]) = s;
    } else if (m < M) {
        for (int t = m; t < M; ++t) {
            float s = 0.f;
            #pragma unroll
            for (int q = 0; q < NSPLIT; ++q) s += g_partial[q][t];
            out[t] = s;
        }
    }
}

extern "C" void kernel_launch(void* const* d_in, const int* in_sizes, int n_in,
                              void* d_out, int out_size)
{
    const float* points      = (const float*)d_in[0];
    const float* positions   = (const float*)d_in[1];
    const float* log_scales  = (const float*)d_in[2];
    const float* intensities = (const float*)d_in[3];
    float* out = (float*)d_out;

    int M = in_sizes[0] / 3;
    int N = in_sizes[3];
    if (M > MAXM) M = MAXM;                 // scratch capacity (problem: M=50000)
    if (N > NSPLIT * NP) N = NSPLIT * NP;   // table capacity (problem: N=1024)

    dim3 grid((M + PTS_PER_BLOCK - 1) / PTS_PER_BLOCK, NSPLIT);
    gauss_eval_kernel<<<grid, BLOCK>>>(points, positions, log_scales, intensities, M, N);

    int nquad = (M + 3) / 4;
    reduce_kernel<<<(nquad + 255) / 256, 256>>>(out, M);
}

// round 16
// speedup vs baseline: 1.5878x; 1.0992x over previous
#include <cuda_runtime.h>
#include <cuda_bf16.h>

// FastGaussianModel: values[m] = sum_n exp(-0.5 * sum_d (p[m,d]-pos[n,d])^2 * iv[n,d]) * I[n]
// log2-domain Horner form per gaussian:
//   e = C + sum_d p_d * (A_d * p_d + B_d),   value += ex2(e) * I
//
// R14 version (atomic tail, no reduce kernel):
//  - fma.rn.f32x2: 2 gaussians per instruction (pair-interleaved smem table)
//  - BLOCK=256, 4 points per thread, NSPLIT=12 -> grid (49,12) = 588 blocks
//    = one clean wave at 4 CTAs/SM
//  - d_out zeroed by cudaMemsetAsync graph node; each slice atomicAdd's its
//    partial directly into out (REDG.ADD, spread addresses, overlapped tail).
//    Removes the ~5.6us reduce launch AND the 4.8MB partial round-trip.
//  - scalar FFMA accumulate (reads packed-e halves directly; no pack MOVs)

#define BLOCK   256
#define PPT     4              // points per thread
#define NSPLIT  12
#define NP      88             // gaussians per slice (12*88=1056 >= 1024, zero-padded)
#define NPAIR   (NP / 2)
#define PTS_PER_BLOCK (BLOCK * PPT)
#define MAXM    50176          // >= M=50000
#define EPS     1e-6f

typedef unsigned long long u64;

__device__ __forceinline__ float ex2f(float x) {
    float y;
    asm("ex2.approx.ftz.f32 %0, %1;" : "=f"(y) : "f"(x));
    return y;
}
__device__ __forceinline__ u64 fma2(u64 a, u64 b, u64 c) {
    u64 d;
    asm("fma.rn.f32x2 %0, %1, %2, %3;" : "=l"(d) : "l"(a), "l"(b), "l"(c));
    return d;
}
__device__ __forceinline__ u64 pack2(float lo, float hi) {
    u64 r;
    asm("mov.b64 %0, {%1, %2};" : "=l"(r) : "f"(lo), "f"(hi));
    return r;
}
__device__ __forceinline__ void unpack2(u64 v, float& lo, float& hi) {
    asm("mov.b64 {%0, %1}, %2;" : "=f"(lo), "=f"(hi) : "l"(v));
}

__global__ __launch_bounds__(BLOCK, 4)
void gauss_eval_kernel(const float* __restrict__ points,
                       const float* __restrict__ positions,
                       const float* __restrict__ log_scales,
                       const float* __restrict__ intensities,
                       float* __restrict__ out,
                       int M, int N)
{
    // Pair-interleaved coefficient table. Each ulonglong2 = two packed f32x2:
    //   TA[j] = { {A0,A0'}, {A1,A1'} }   TB[j] = { {A2,A2'}, { C, C' } }
    //   TC[j] = { {B0,B0'}, {B1,B1'} }   TD[j] = { {B2,B2'}, { I, I' } }
    __shared__ ulonglong2 TA[NPAIR], TB[NPAIR], TC[NPAIR], TD[NPAIR];

    const float L = 1.4426950408889634f;   // log2(e)
    const int tid = threadIdx.x;

    // ---- per-block precompute of this N-slice's table ----
    if (tid < NP) {
        int g = blockIdx.y * NP + tid;
        float A0 = 0.f, A1 = 0.f, A2 = 0.f, C = 0.f;
        float B0 = 0.f, B1 = 0.f, B2 = 0.f, I = 0.f;  // zero pad: ex2(0)*0 = 0
        if (g < N) {
            float ls0 = log_scales[3*g + 0];
            float ls1 = log_scales[3*g + 1];
            float ls2 = log_scales[3*g + 2];
            float q0  = positions[3*g + 0];
            float q1  = positions[3*g + 1];
            float q2  = positions[3*g + 2];
            I = intensities[g];

            float iv0 = 1.0f / (expf(2.0f * ls0) + EPS);
            float iv1 = 1.0f / (expf(2.0f * ls1) + EPS);
            float iv2 = 1.0f / (expf(2.0f * ls2) + EPS);

            A0 = -0.5f * L * iv0;
            A1 = -0.5f * L * iv1;
            A2 = -0.5f * L * iv2;
            B0 = L * iv0 * q0;
            B1 = L * iv1 * q1;
            B2 = L * iv2 * q2;
            C  = A0*q0*q0 + A1*q1*q1 + A2*q2*q2;
        }
        int j = tid >> 1, l = tid & 1;
        float* fTA = (float*)TA;  float* fTB = (float*)TB;
        float* fTC = (float*)TC;  float* fTD = (float*)TD;
        fTA[4*j + 0 + l] = A0;  fTA[4*j + 2 + l] = A1;
        fTB[4*j + 0 + l] = A2;  fTB[4*j + 2 + l] = C;
        fTC[4*j + 0 + l] = B0;  fTC[4*j + 2 + l] = B1;
        fTD[4*j + 0 + l] = B2;  fTD[4*j + 2 + l] = I;
    }
    __syncthreads();

    // ---- four points per thread (broadcast-packed coords, 3 u64 per point) ----
    int mbase = blockIdx.x * PTS_PER_BLOCK + tid;
    int midx[PPT];
    u64 P0[PPT], P1[PPT], P2[PPT];
    float accA[PPT], accB[PPT];
    #pragma unroll
    for (int k = 0; k < PPT; ++k) {
        int m = mbase + k * BLOCK;
        midx[k] = m;
        int mc = m < M ? m : M - 1;
        float p0 = points[3*mc + 0];
        float p1 = points[3*mc + 1];
        float p2 = points[3*mc + 2];
        P0[k] = pack2(p0, p0);
        P1[k] = pack2(p1, p1);
        P2[k] = pack2(p2, p2);
        accA[k] = 0.0f;
        accB[k] = 0.0f;
    }

    #pragma unroll 4
    for (int j = 0; j < NPAIR; ++j) {
        ulonglong2 ta = TA[j];
        ulonglong2 tb = TB[j];
        ulonglong2 tc = TC[j];
        ulonglong2 td = TD[j];
        float I0, I1;
        unpack2(td.y, I0, I1);   // register-half read, no real MOV needed

        #pragma unroll
        for (int k = 0; k < PPT; ++k) {
            // t_d = A_d*p_d + B_d (parallel), e = C + sum p_d * t_d
            u64 t0 = fma2(ta.x, P0[k], tc.x);
            u64 t1 = fma2(ta.y, P1[k], tc.y);
            u64 t2 = fma2(tb.x, P2[k], td.x);
            u64 e  = fma2(P0[k], t0, tb.y);
            e = fma2(P1[k], t1, e);
            e = fma2(P2[k], t2, e);

            float e0, e1;
            unpack2(e, e0, e1);
            accA[k] = fmaf(ex2f(e0), I0, accA[k]);
            accB[k] = fmaf(ex2f(e1), I1, accB[k]);
        }
    }

    // ---- atomic tail: slice partials sum directly into out (REDG.ADD) ----
    #pragma unroll
    for (int k = 0; k < PPT; ++k) {
        if (midx[k] < M) atomicAdd(&out[midx[k]], accA[k] + accB[k]);
    }
}

extern "C" void kernel_launch(void* const* d_in, const int* in_sizes, int n_in,
                              void* d_out, int out_size)
{
    const float* points      = (const float*)d_in[0];
    const float* positions   = (const float*)d_in[1];
    const float* log_scales  = (const float*)d_in[2];
    const float* intensities = (const float*)d_in[3];
    float* out = (float*)d_out;

    int M = in_sizes[0] / 3;
    int N = in_sizes[3];
    if (M > MAXM) M = MAXM;                 // grid-shape guard (problem: M=50000)
    if (N > NSPLIT * NP) N = NSPLIT * NP;   // table capacity (problem: N=1024)

    // zero the accumulation target (graph-capturable memset node)
    cudaMemsetAsync(d_out, 0, (size_t)out_size * sizeof(float));

    dim3 grid((M + PTS_PER_BLOCK - 1) / PTS_PER_BLOCK, NSPLIT);
    gauss_eval_kernel<<<grid, BLOCK>>>(points, positions, log_scales, intensities,
                                       out, M, N);
}